// round 12
// baseline (speedup 1.0000x reference)
#include <cuda_runtime.h>
#include <cuda_bf16.h>
#include <cstdint>

#define TOK   256
#define INF   4096
#define OUTF  4096
#define NOUT  32

#define NCTA    148
#define NUNITS  2048            // (nt in [0,64)) x (k in [0,32))
#define STAGES  4

#define AHALF   16384           // one A block: 128m x 128k int8
#define BSZ     8192            // one B block: 64n x 128k int8
#define STG_SZ  40960           // A0 + A1 + B per stage
#define SA_OFF(s) ((s) * STG_SZ)
#define MBF_OFF  (STG_SZ * STAGES)          // 163840: full[4]
#define MBE_OFF  (MBF_OFF + 32)             // empty[4]
#define SCNT_OFF (MBF_OFF + 64)             // pack counter
#define SMEM_TOTAL (MBF_OFF + 128)

// ---------------- scratch (no cudaMalloc allowed) ----------------
__device__ __align__(128) int8_t g_xq[TOK * INF];          // A blocks (1MB)
__device__ __align__(128) int8_t g_w8[(size_t)OUTF * INF]; // B blocks (16MB)
__device__ float g_xs[TOK];
__device__ int   g_qcnt;    // quantized rows done (0..256)
__device__ int   g_pfcnt;   // prefill blocks done (0..256)

__device__ __forceinline__ uint32_t smem_to_u32(const void* p) {
    uint32_t a;
    asm("{ .reg .u64 t; cvta.to.shared.u64 t, %1; cvt.u32.u64 %0, t; }" : "=r"(a) : "l"(p));
    return a;
}
__device__ __forceinline__ int ld_acq_gpu(const int* p) {
    int v; asm volatile("ld.acquire.gpu.global.s32 %0, [%1];" : "=r"(v) : "l"(p) : "memory"); return v;
}
__device__ __forceinline__ void red_rel_gpu(int* p, int v) {
    asm volatile("red.release.gpu.global.add.s32 [%0], %1;" :: "l"(p), "r"(v) : "memory");
}
__device__ __forceinline__ int ld_acq_sh(uint32_t a) {
    int v; asm volatile("ld.acquire.cta.shared.s32 %0, [%1];" : "=r"(v) : "r"(a) : "memory"); return v;
}
__device__ __forceinline__ void red_rel_sh(uint32_t a, int v) {
    asm volatile("red.release.cta.shared.add.s32 [%0], %1;" :: "r"(a), "r"(v) : "memory");
}

#define MBARRIER_INIT(mbar, count) \
    asm volatile("mbarrier.init.shared.b64 [%0], %1;" :: "r"((uint32_t)(mbar)), "r"((uint32_t)(count)) : "memory")
#define MBARRIER_ARRIVE(mbar) \
    asm volatile("mbarrier.arrive.shared.b64 _, [%0];" :: "r"((uint32_t)(mbar)) : "memory")
#define MBARRIER_EXPECT_TX(mbar, bytes) \
    asm volatile("mbarrier.arrive.expect_tx.shared.b64 _, [%0], %1;" :: "r"((uint32_t)(mbar)), "r"((uint32_t)(bytes)) : "memory")
#define BULK_G2S(dst, src, bytes, mbar) \
    asm volatile("cp.async.bulk.shared::cluster.global.mbarrier::complete_tx::bytes [%0], [%1], %2, [%3];" \
        :: "r"((uint32_t)(dst)), "l"(src), "r"((uint32_t)(bytes)), "r"((uint32_t)(mbar)) : "memory")
#define FENCE_PROXY_ASYNC() asm volatile("fence.proxy.async;" ::: "memory")

#define MBARRIER_WAIT_PARITY(mbar_smem_addr, phase_parity) do { \
    uint32_t _mbar = (uint32_t)(mbar_smem_addr); \
    uint32_t _parity = (uint32_t)(phase_parity); \
    uint32_t _done; \
    asm volatile("{\n\t.reg .pred p;\n\t" \
        "mbarrier.try_wait.parity.acquire.cta.shared::cta.b64 p, [%1], %2;\n\t" \
        "selp.b32 %0, 1, 0, p;\n\t}" : "=r"(_done) : "r"(_mbar), "r"(_parity) : "memory"); \
    if (!_done) { \
        asm volatile("{\n\t.reg .pred P1;\n\t" \
            "WAIT_LOOP_%=:\n\t" \
            "mbarrier.try_wait.parity.acquire.cta.shared::cta.b64 P1, [%0], %1, 0x989680;\n\t" \
            "@P1 bra.uni WAIT_DONE_%=;\n\t" \
            "bra.uni WAIT_LOOP_%=;\n\t" \
            "WAIT_DONE_%=:\n\t}" :: "r"(_mbar), "r"(_parity) : "memory"); \
    } \
} while (0)

// ---------------- reset counters (graph-replayed each launch) ----------------
__global__ void reset_kernel() { g_qcnt = 0; g_pfcnt = 0; }

// ---------------- fused persistent kernel ----------------
// 148 CTAs x 544 threads. warps 0-15 consumers (4m x 4n over m256 n64 tile),
// warp 16 = TMA producer. Prologue: quantize + outlier prefill + pack first 4
// B blocks. Loop: lazy-pack B block for unit c+4, compute unit c.
__global__ __launch_bounds__(544, 1) void fused_kernel(const float* __restrict__ x,
                                                       const int* __restrict__ w,
                                                       const int* __restrict__ oidx,
                                                       const float* __restrict__ ow,
                                                       const float* __restrict__ bias,
                                                       const float* __restrict__ wscale,
                                                       float* __restrict__ out) {
    extern __shared__ char smem[];
    const uint32_t sb = smem_to_u32(smem);
    const int tid = threadIdx.x;
    const int lane = tid & 31, wid = tid >> 5;
    const int bid = blockIdx.x;

    const int g0 = (int)(((long long)bid * NUNITS) / NCTA);
    const int g1 = (int)(((long long)(bid + 1) * NUNITS) / NCTA);
    const int nunits = g1 - g0;

    __shared__ float s_red[8];
    __shared__ float s_scale;
    __shared__ int   s_oi[NOUT];
    __shared__ float s_owT[NOUT * 128];
    __shared__ float s_xo[32 * NOUT];
    __shared__ float s_b[128];

    if (tid == 0) {
#pragma unroll
        for (int s = 0; s < STAGES; s++) {
            MBARRIER_INIT(sb + MBF_OFF + s * 8, 1);
            MBARRIER_INIT(sb + MBE_OFF + s * 8, 512);
        }
        *(int*)(smem + SCNT_OFF) = 0;
    }
    if (tid < NOUT) s_oi[tid] = oidx[tid];
    __syncthreads();

    // ================= prologue =================
    // ---- quantize rows bid, bid+148 ----
    const int nrows = 1 + ((bid + NCTA) < TOK ? 1 : 0);
    for (int rr = 0; rr < nrows; rr++) {
        const int r = bid + rr * NCTA;
        float4 f[4];
        if (tid < 256) {
            const float4* xr = (const float4*)(x + (size_t)r * INF);
#pragma unroll
            for (int t = 0; t < 4; t++) f[t] = xr[tid * 4 + t];
            const int kbase = tid * 16;
            unsigned mz = 0;
#pragma unroll
            for (int j = 0; j < NOUT; j++) {
                unsigned d = (unsigned)(s_oi[j] - kbase);
                if (d < 16u) mz |= 1u << d;
            }
#pragma unroll
            for (int t = 0; t < 4; t++) {
                if (mz & (1u << (t * 4 + 0))) f[t].x = 0.0f;
                if (mz & (1u << (t * 4 + 1))) f[t].y = 0.0f;
                if (mz & (1u << (t * 4 + 2))) f[t].z = 0.0f;
                if (mz & (1u << (t * 4 + 3))) f[t].w = 0.0f;
            }
            float mx = 0.0f;
#pragma unroll
            for (int t = 0; t < 4; t++)
                mx = fmaxf(mx, fmaxf(fmaxf(fabsf(f[t].x), fabsf(f[t].y)),
                                     fmaxf(fabsf(f[t].z), fabsf(f[t].w))));
#pragma unroll
            for (int d = 16; d > 0; d >>= 1) mx = fmaxf(mx, __shfl_xor_sync(0xFFFFFFFFu, mx, d));
            if (lane == 0 && wid < 8) s_red[wid] = mx;
        }
        __syncthreads();
        if (tid == 0) {
            float m = s_red[0];
#pragma unroll
            for (int i = 1; i < 8; i++) m = fmaxf(m, s_red[i]);
            s_scale = m;
            g_xs[r] = m;
        }
        __syncthreads();
        if (tid < 256) {
            const float r127 = 127.0f / fmaxf(s_scale, 1e-8f);
            uint32_t pk[4];
#pragma unroll
            for (int t = 0; t < 4; t++) {
                int q0 = min(max(__float2int_rn(f[t].x * r127), -127), 127);
                int q1 = min(max(__float2int_rn(f[t].y * r127), -127), 127);
                int q2 = min(max(__float2int_rn(f[t].z * r127), -127), 127);
                int q3 = min(max(__float2int_rn(f[t].w * r127), -127), 127);
                uint32_t p0 = __byte_perm((uint32_t)q0, (uint32_t)q1, 0x0040);
                uint32_t p1 = __byte_perm((uint32_t)q2, (uint32_t)q3, 0x0040);
                pk[t] = __byte_perm(p0, p1, 0x5410);
            }
            const int mt = r >> 7, rw = r & 127;
            const int cb = tid >> 3, cp = tid & 7;
            int8_t* dst = g_xq + ((size_t)(mt * 32 + cb) << 14) + rw * 128 + (((cp ^ (rw & 7))) << 4);
            *(uint4*)dst = make_uint4(pk[0], pk[1], pk[2], pk[3]);
        }
    }
    __syncthreads();
    if (tid == 0) red_rel_gpu(&g_qcnt, nrows);

    // ---- outlier + bias prefill blocks bid, bid+148 ----
    for (int ib = 0; ib < nrows; ib++) {   // same count pattern: 256 blocks
        const int idx = bid + ib * NCTA;
        const int obase = (idx & 31) * 128;
        const int tbase = (idx >> 5) * 32;
        if (tid < 128) s_b[tid] = bias[obase + tid];
        if (tid < 256) {
#pragma unroll
            for (int t = 0; t < 4; t++) {
                int i = tid + t * 256;
                int o = i >> 3, j4 = i & 7;
                float4 fv = ((const float4*)ow)[(size_t)obase * 8 + i];
                s_owT[(j4 * 4 + 0) * 128 + o] = fv.x;
                s_owT[(j4 * 4 + 1) * 128 + o] = fv.y;
                s_owT[(j4 * 4 + 2) * 128 + o] = fv.z;
                s_owT[(j4 * 4 + 3) * 128 + o] = fv.w;
            }
#pragma unroll
            for (int t = 0; t < 4; t++) {
                int i = tid + t * 256;
                int r = i >> 5, j = i & 31;
                s_xo[i] = x[(size_t)(tbase + r) * INF + s_oi[j]];
            }
        }
        __syncthreads();
        if (tid < 256) {
            const int ty = tid >> 5, tx = tid & 31;
            float acc[4][4];
#pragma unroll
            for (int tt = 0; tt < 4; tt++)
#pragma unroll
                for (int c = 0; c < 4; c++) acc[tt][c] = s_b[tx + c * 32];
#pragma unroll
            for (int j = 0; j < NOUT; j++) {
                float wv[4];
#pragma unroll
                for (int c = 0; c < 4; c++) wv[c] = s_owT[j * 128 + tx + c * 32];
#pragma unroll
                for (int tt = 0; tt < 4; tt++) {
                    float xv = s_xo[(ty * 4 + tt) * NOUT + j];
#pragma unroll
                    for (int c = 0; c < 4; c++) acc[tt][c] += xv * wv[c];
                }
            }
#pragma unroll
            for (int tt = 0; tt < 4; tt++)
#pragma unroll
                for (int c = 0; c < 4; c++)
                    out[(size_t)(tbase + ty * 4 + tt) * OUTF + obase + tx + c * 32] = acc[tt][c];
        }
        __syncthreads();
    }
    if (tid == 0) red_rel_gpu(&g_pfcnt, nrows);

    // ---- prologue pack: first min(4, nunits) B blocks of own range ----
    const int npro = nunits < 4 ? nunits : 4;
    for (int j = 0; j < npro; j++) {
        const int g = g0 + j;
        const int nt = g >> 5, k = g & 31;
        if (tid < 256) {
#pragma unroll
            for (int t = 0; t < 2; t++) {
                int u = tid + t * 256;
                int r = u >> 3, cc = u & 7;
                const int* src = w + (size_t)(nt * 64 + r) * INF + k * 128 + cc * 16;
                int4 v0 = *(const int4*)(src);
                int4 v1 = *(const int4*)(src + 4);
                int4 v2 = *(const int4*)(src + 8);
                int4 v3 = *(const int4*)(src + 12);
                uint32_t a0 = __byte_perm(__byte_perm((uint32_t)v0.x, (uint32_t)v0.y, 0x0040),
                                          __byte_perm((uint32_t)v0.z, (uint32_t)v0.w, 0x0040), 0x5410);
                uint32_t a1 = __byte_perm(__byte_perm((uint32_t)v1.x, (uint32_t)v1.y, 0x0040),
                                          __byte_perm((uint32_t)v1.z, (uint32_t)v1.w, 0x0040), 0x5410);
                uint32_t a2 = __byte_perm(__byte_perm((uint32_t)v2.x, (uint32_t)v2.y, 0x0040),
                                          __byte_perm((uint32_t)v2.z, (uint32_t)v2.w, 0x0040), 0x5410);
                uint32_t a3 = __byte_perm(__byte_perm((uint32_t)v3.x, (uint32_t)v3.y, 0x0040),
                                          __byte_perm((uint32_t)v3.z, (uint32_t)v3.w, 0x0040), 0x5410);
                int8_t* dst = g_w8 + ((size_t)(nt * 32 + k) << 13) + r * 128 + ((cc ^ (r & 7)) << 4);
                *(uint4*)dst = make_uint4(a0, a1, a2, a3);
            }
        }
    }
    __syncthreads();   // packs + smem counter visible to producer warp

    // ================= main phase =================
    if (wid == 16) {
        // ---- producer (lane 0): TMA ring ----
        if (lane == 0) {
            while (ld_acq_gpu(&g_qcnt) != TOK) __nanosleep(64);
#pragma unroll 1
            for (int it = 0; it < nunits; it++) {
                const int g = g0 + it;
                const int fs = it & (STAGES - 1);
                if (it >= STAGES) {
                    MBARRIER_WAIT_PARITY(sb + MBE_OFF + fs * 8, ((it >> 2) - 1) & 1);
                    while (ld_acq_sh(sb + SCNT_OFF) < 8 * (it - 3)) __nanosleep(32);
                }
                const int nt = g >> 5, k = g & 31;
                FENCE_PROXY_ASYNC();
                const uint32_t mb = sb + MBF_OFF + fs * 8;
                MBARRIER_EXPECT_TX(mb, STG_SZ);
                BULK_G2S(sb + SA_OFF(fs),          g_xq + ((size_t)k << 14),        AHALF, mb);
                BULK_G2S(sb + SA_OFF(fs) + AHALF,  g_xq + ((size_t)(32 + k) << 14), AHALF, mb);
                BULK_G2S(sb + SA_OFF(fs) + 2 * AHALF, g_w8 + ((size_t)(nt * 32 + k) << 13), BSZ, mb);
            }
        }
    } else {
        // ---- consumers: 16 warps, 4m x 4n over m256 x n64 ----
        const int wm = wid >> 2, wn = wid & 3;
        const float inv = 1.0f / 16129.0f;
        const int grp = lane >> 2, qid = lane & 3;
        bool pfok = false;

        int acc[4][2][4];
#pragma unroll
        for (int i = 0; i < 4; i++)
#pragma unroll
            for (int j = 0; j < 2; j++)
#pragma unroll
                for (int q = 0; q < 4; q++) acc[i][j][q] = 0;

#pragma unroll 1
        for (int c = 0; c < nunits; c++) {
            const int g = g0 + c;
            const int s = c & (STAGES - 1);
            MBARRIER_WAIT_PARITY(sb + MBF_OFF + s * 8, (c >> 2) & 1);

            // ---- lazy pack of unit c+4 (warps 0-7) ----
            if (tid < 256 && c + 4 < nunits) {
                const int gp = g0 + c + 4;
                const int pnt = gp >> 5, pk2 = gp & 31;
#pragma unroll
                for (int t = 0; t < 2; t++) {
                    int u = tid + t * 256;
                    int r = u >> 3, cc = u & 7;
                    const int* src = w + (size_t)(pnt * 64 + r) * INF + pk2 * 128 + cc * 16;
                    int4 v0 = *(const int4*)(src);
                    int4 v1 = *(const int4*)(src + 4);
                    int4 v2 = *(const int4*)(src + 8);
                    int4 v3 = *(const int4*)(src + 12);
                    uint32_t a0 = __byte_perm(__byte_perm((uint32_t)v0.x, (uint32_t)v0.y, 0x0040),
                                              __byte_perm((uint32_t)v0.z, (uint32_t)v0.w, 0x0040), 0x5410);
                    uint32_t a1 = __byte_perm(__byte_perm((uint32_t)v1.x, (uint32_t)v1.y, 0x0040),
                                              __byte_perm((uint32_t)v1.z, (uint32_t)v1.w, 0x0040), 0x5410);
                    uint32_t a2 = __byte_perm(__byte_perm((uint32_t)v2.x, (uint32_t)v2.y, 0x0040),
                                              __byte_perm((uint32_t)v2.z, (uint32_t)v2.w, 0x0040), 0x5410);
                    uint32_t a3 = __byte_perm(__byte_perm((uint32_t)v3.x, (uint32_t)v3.y, 0x0040),
                                              __byte_perm((uint32_t)v3.z, (uint32_t)v3.w, 0x0040), 0x5410);
                    int8_t* dst = g_w8 + ((size_t)(pnt * 32 + pk2) << 13) + r * 128 + ((cc ^ (r & 7)) << 4);
                    *(uint4*)dst = make_uint4(a0, a1, a2, a3);
                }
                __syncwarp();
                if (lane == 0) red_rel_sh(sb + SCNT_OFF, 1);
            }

            // ---- compute unit (proven fragment/swizzle math) ----
#pragma unroll
            for (int ksl = 0; ksl < 4; ksl++) {
                uint32_t a[4][4];
#pragma unroll
                for (int mf = 0; mf < 4; mf++) {
                    int absrow = wm * 64 + mf * 16 + (lane & 15);
                    int blk = absrow >> 7, inner = absrow & 127;
                    int kc = 2 * ksl + (lane >> 4);
                    uint32_t ad = sb + SA_OFF(s) + blk * AHALF +
                                  (uint32_t)(inner * 128 + ((kc ^ (inner & 7)) << 4));
                    asm volatile("ldmatrix.sync.aligned.m8n8.x4.shared.b16 {%0,%1,%2,%3}, [%4];"
                        : "=r"(a[mf][0]), "=r"(a[mf][1]), "=r"(a[mf][2]), "=r"(a[mf][3])
                        : "r"(ad));
                }
                uint32_t b[4];
                {
                    int n = wn * 16 + (lane & 7) + ((lane >> 4) << 3);
                    int kc = 2 * ksl + ((lane >> 3) & 1);
                    uint32_t bd = sb + SA_OFF(s) + 2 * AHALF +
                                  (uint32_t)(n * 128 + ((kc ^ (n & 7)) << 4));
                    asm volatile("ldmatrix.sync.aligned.m8n8.x4.shared.b16 {%0,%1,%2,%3}, [%4];"
                        : "=r"(b[0]), "=r"(b[1]), "=r"(b[2]), "=r"(b[3])
                        : "r"(bd));
                }
#pragma unroll
                for (int mf = 0; mf < 4; mf++)
#pragma unroll
                    for (int nf = 0; nf < 2; nf++) {
                        asm volatile(
                            "mma.sync.aligned.m16n8k32.row.col.s32.s8.s8.s32 "
                            "{%0,%1,%2,%3}, {%4,%5,%6,%7}, {%8,%9}, {%0,%1,%2,%3};"
                            : "+r"(acc[mf][nf][0]), "+r"(acc[mf][nf][1]),
                              "+r"(acc[mf][nf][2]), "+r"(acc[mf][nf][3])
                            : "r"(a[mf][0]), "r"(a[mf][1]), "r"(a[mf][2]), "r"(a[mf][3]),
                              "r"(b[nf * 2]), "r"(b[nf * 2 + 1]));
                    }
            }
            MBARRIER_ARRIVE(sb + MBE_OFF + s * 8);

            // ---- epilogue at nt boundary or range end ----
            if (c + 1 == nunits || ((g + 1) & 31) == 0) {
                if (!pfok) {
                    while (ld_acq_gpu(&g_pfcnt) != 256) __nanosleep(64);
                    pfok = true;
                }
                const int nbase = (g >> 5) * 64;
#pragma unroll
                for (int mf = 0; mf < 4; mf++) {
                    const int m0 = wm * 64 + mf * 16 + grp;
                    const float s0 = g_xs[m0] * inv;
                    const float s1 = g_xs[m0 + 8] * inv;
#pragma unroll
                    for (int nf = 0; nf < 2; nf++) {
                        const int o = nbase + wn * 16 + nf * 8 + qid * 2;
                        const float2 wsv = *(const float2*)(wscale + o);
                        float* p0 = out + (size_t)m0 * OUTF + o;
                        float* p1 = out + (size_t)(m0 + 8) * OUTF + o;
                        atomicAdd(p0,     (float)acc[mf][nf][0] * (s0 * wsv.x));
                        atomicAdd(p0 + 1, (float)acc[mf][nf][1] * (s0 * wsv.y));
                        atomicAdd(p1,     (float)acc[mf][nf][2] * (s1 * wsv.x));
                        atomicAdd(p1 + 1, (float)acc[mf][nf][3] * (s1 * wsv.y));
                    }
                }
#pragma unroll
                for (int i = 0; i < 4; i++)
#pragma unroll
                    for (int j = 0; j < 2; j++)
#pragma unroll
                        for (int q = 0; q < 4; q++) acc[i][j][q] = 0;
            }
        }
    }
}

// ---------------- launch ----------------
extern "C" void kernel_launch(void* const* d_in, const int* in_sizes, int n_in,
                              void* d_out, int out_size) {
    const float* x    = (const float*)d_in[0];
    const int*   w    = (const int*)d_in[1];
    const float* ws   = (const float*)d_in[2];
    const int*   oidx = (const int*)d_in[3];
    const float* ow   = (const float*)d_in[4];
    const float* bias = (const float*)d_in[5];
    float* out = (float*)d_out;

    cudaFuncSetAttribute(fused_kernel, cudaFuncAttributeMaxDynamicSharedMemorySize, SMEM_TOTAL);

    reset_kernel<<<1, 1>>>();
    fused_kernel<<<NCTA, 544, SMEM_TOTAL>>>(x, w, oidx, ow, bias, ws, out);
}

// round 13
// speedup vs baseline: 1.0803x; 1.0803x over previous
#include <cuda_runtime.h>
#include <cuda_bf16.h>
#include <cstdint>

#define TOK   256
#define INF   4096
#define OUTF  4096
#define NOUT  32

#define NCTA    148
#define NUNITS  2048            // (nt in [0,64)) x (k in [0,32))
#define STAGES  4

#define AHALF   16384           // one A block: 128m x 128k int8
#define BSZ     8192            // one B block: 64n x 128k int8
#define STG_SZ  40960           // A0 + A1 + B per stage
#define SA_OFF(s) ((s) * STG_SZ)
#define MBF_OFF  (STG_SZ * STAGES)          // 163840: full[4]
#define MBE_OFF  (MBF_OFF + 32)             // empty[4]
#define SMEM_TOTAL (MBF_OFF + 128)

// ---------------- scratch (no cudaMalloc allowed) ----------------
__device__ __align__(128) int8_t g_xq[TOK * INF];   // A blocks (1MB)
__device__ float g_xs[TOK];
__device__ int   g_qcnt;    // quantized rows done (0..256)
__device__ int   g_pfcnt;   // prefill blocks done (0..256)

__device__ __forceinline__ uint32_t smem_to_u32(const void* p) {
    uint32_t a;
    asm("{ .reg .u64 t; cvta.to.shared.u64 t, %1; cvt.u32.u64 %0, t; }" : "=r"(a) : "l"(p));
    return a;
}
__device__ __forceinline__ int ld_acq_gpu(const int* p) {
    int v; asm volatile("ld.acquire.gpu.global.s32 %0, [%1];" : "=r"(v) : "l"(p) : "memory"); return v;
}
__device__ __forceinline__ void red_rel_gpu(int* p, int v) {
    asm volatile("red.release.gpu.global.add.s32 [%0], %1;" :: "l"(p), "r"(v) : "memory");
}

#define MBARRIER_INIT(mbar, count) \
    asm volatile("mbarrier.init.shared.b64 [%0], %1;" :: "r"((uint32_t)(mbar)), "r"((uint32_t)(count)) : "memory")
#define MBARRIER_ARRIVE(mbar) \
    asm volatile("mbarrier.arrive.release.cta.shared.b64 _, [%0];" :: "r"((uint32_t)(mbar)) : "memory")
#define MBARRIER_EXPECT_TX(mbar, bytes) \
    asm volatile("mbarrier.arrive.expect_tx.shared.b64 _, [%0], %1;" :: "r"((uint32_t)(mbar)), "r"((uint32_t)(bytes)) : "memory")
#define BULK_G2S(dst, src, bytes, mbar) \
    asm volatile("cp.async.bulk.shared::cluster.global.mbarrier::complete_tx::bytes [%0], [%1], %2, [%3];" \
        :: "r"((uint32_t)(dst)), "l"(src), "r"((uint32_t)(bytes)), "r"((uint32_t)(mbar)) : "memory")
#define FENCE_PROXY_ASYNC() asm volatile("fence.proxy.async;" ::: "memory")

#define MBARRIER_WAIT_PARITY(mbar_smem_addr, phase_parity) do { \
    uint32_t _mbar = (uint32_t)(mbar_smem_addr); \
    uint32_t _parity = (uint32_t)(phase_parity); \
    uint32_t _done; \
    asm volatile("{\n\t.reg .pred p;\n\t" \
        "mbarrier.try_wait.parity.acquire.cta.shared::cta.b64 p, [%1], %2;\n\t" \
        "selp.b32 %0, 1, 0, p;\n\t}" : "=r"(_done) : "r"(_mbar), "r"(_parity) : "memory"); \
    if (!_done) { \
        asm volatile("{\n\t.reg .pred P1;\n\t" \
            "WAIT_LOOP_%=:\n\t" \
            "mbarrier.try_wait.parity.acquire.cta.shared::cta.b64 P1, [%0], %1, 0x989680;\n\t" \
            "@P1 bra.uni WAIT_DONE_%=;\n\t" \
            "bra.uni WAIT_LOOP_%=;\n\t" \
            "WAIT_DONE_%=:\n\t}" :: "r"(_mbar), "r"(_parity) : "memory"); \
    } \
} while (0)

// ---------------- reset counters (graph-replayed each launch) ----------------
__global__ void reset_kernel() { g_qcnt = 0; g_pfcnt = 0; }

// ---------------- fused persistent kernel ----------------
// 148 CTAs x 544 threads (17 warps). Warps 0-15: pure IMMA consumers
// (4m x 4n over m256 x n64). Warp 16: producer -- TMA for A, direct
// w(int32) -> smem(int8,swizzled) pack for B.
__global__ __launch_bounds__(544, 1) void fused_kernel(const float* __restrict__ x,
                                                       const int* __restrict__ w,
                                                       const int* __restrict__ oidx,
                                                       const float* __restrict__ ow,
                                                       const float* __restrict__ bias,
                                                       const float* __restrict__ wscale,
                                                       float* __restrict__ out) {
    extern __shared__ char smem[];
    const uint32_t sb = smem_to_u32(smem);
    const int tid = threadIdx.x;
    const int lane = tid & 31, wid = tid >> 5;
    const int bid = blockIdx.x;

    const int g0 = (int)(((long long)bid * NUNITS) / NCTA);
    const int g1 = (int)(((long long)(bid + 1) * NUNITS) / NCTA);
    const int nunits = g1 - g0;

    __shared__ float s_red[8];
    __shared__ float s_scale;
    __shared__ int   s_oi[NOUT];
    __shared__ float s_owT[NOUT * 128];
    __shared__ float s_xo[32 * NOUT];
    __shared__ float s_b[128];

    if (tid == 0) {
#pragma unroll
        for (int s = 0; s < STAGES; s++) {
            MBARRIER_INIT(sb + MBF_OFF + s * 8, 2);    // expect_tx arrival + post-STS arrival
            MBARRIER_INIT(sb + MBE_OFF + s * 8, 512);  // all consumer threads
        }
    }
    if (tid < NOUT) s_oi[tid] = oidx[tid];
    __syncthreads();

    // ================= prologue (cheap, ~2 rows + 2 blocks per CTA) =================
    const int nrows = 1 + ((bid + NCTA) < TOK ? 1 : 0);
    for (int rr = 0; rr < nrows; rr++) {
        const int r = bid + rr * NCTA;
        float4 f[4];
        if (tid < 256) {
            const float4* xr = (const float4*)(x + (size_t)r * INF);
#pragma unroll
            for (int t = 0; t < 4; t++) f[t] = xr[tid * 4 + t];
            const int kbase = tid * 16;
            unsigned mz = 0;
#pragma unroll
            for (int j = 0; j < NOUT; j++) {
                unsigned d = (unsigned)(s_oi[j] - kbase);
                if (d < 16u) mz |= 1u << d;
            }
#pragma unroll
            for (int t = 0; t < 4; t++) {
                if (mz & (1u << (t * 4 + 0))) f[t].x = 0.0f;
                if (mz & (1u << (t * 4 + 1))) f[t].y = 0.0f;
                if (mz & (1u << (t * 4 + 2))) f[t].z = 0.0f;
                if (mz & (1u << (t * 4 + 3))) f[t].w = 0.0f;
            }
            float mx = 0.0f;
#pragma unroll
            for (int t = 0; t < 4; t++)
                mx = fmaxf(mx, fmaxf(fmaxf(fabsf(f[t].x), fabsf(f[t].y)),
                                     fmaxf(fabsf(f[t].z), fabsf(f[t].w))));
#pragma unroll
            for (int d = 16; d > 0; d >>= 1) mx = fmaxf(mx, __shfl_xor_sync(0xFFFFFFFFu, mx, d));
            if (lane == 0 && wid < 8) s_red[wid] = mx;
        }
        __syncthreads();
        if (tid == 0) {
            float m = s_red[0];
#pragma unroll
            for (int i = 1; i < 8; i++) m = fmaxf(m, s_red[i]);
            s_scale = m;
            g_xs[r] = m;
        }
        __syncthreads();
        if (tid < 256) {
            const float r127 = 127.0f / fmaxf(s_scale, 1e-8f);
            uint32_t pk[4];
#pragma unroll
            for (int t = 0; t < 4; t++) {
                int q0 = min(max(__float2int_rn(f[t].x * r127), -127), 127);
                int q1 = min(max(__float2int_rn(f[t].y * r127), -127), 127);
                int q2 = min(max(__float2int_rn(f[t].z * r127), -127), 127);
                int q3 = min(max(__float2int_rn(f[t].w * r127), -127), 127);
                uint32_t p0 = __byte_perm((uint32_t)q0, (uint32_t)q1, 0x0040);
                uint32_t p1 = __byte_perm((uint32_t)q2, (uint32_t)q3, 0x0040);
                pk[t] = __byte_perm(p0, p1, 0x5410);
            }
            const int mt = r >> 7, rw = r & 127;
            const int cb = tid >> 3, cp = tid & 7;
            int8_t* dst = g_xq + ((size_t)(mt * 32 + cb) << 14) + rw * 128 + (((cp ^ (rw & 7))) << 4);
            *(uint4*)dst = make_uint4(pk[0], pk[1], pk[2], pk[3]);
        }
    }
    __syncthreads();
    if (tid == 0) red_rel_gpu(&g_qcnt, nrows);

    // ---- outlier + bias prefill blocks bid, bid+148 ----
    for (int ib = 0; ib < nrows; ib++) {
        const int idx = bid + ib * NCTA;
        const int obase = (idx & 31) * 128;
        const int tbase = (idx >> 5) * 32;
        if (tid < 128) s_b[tid] = bias[obase + tid];
        if (tid < 256) {
#pragma unroll
            for (int t = 0; t < 4; t++) {
                int i = tid + t * 256;
                int o = i >> 3, j4 = i & 7;
                float4 fv = ((const float4*)ow)[(size_t)obase * 8 + i];
                s_owT[(j4 * 4 + 0) * 128 + o] = fv.x;
                s_owT[(j4 * 4 + 1) * 128 + o] = fv.y;
                s_owT[(j4 * 4 + 2) * 128 + o] = fv.z;
                s_owT[(j4 * 4 + 3) * 128 + o] = fv.w;
            }
#pragma unroll
            for (int t = 0; t < 4; t++) {
                int i = tid + t * 256;
                int r = i >> 5, j = i & 31;
                s_xo[i] = x[(size_t)(tbase + r) * INF + s_oi[j]];
            }
        }
        __syncthreads();
        if (tid < 256) {
            const int ty = tid >> 5, tx = tid & 31;
            float acc[4][4];
#pragma unroll
            for (int tt = 0; tt < 4; tt++)
#pragma unroll
                for (int c = 0; c < 4; c++) acc[tt][c] = s_b[tx + c * 32];
#pragma unroll
            for (int j = 0; j < NOUT; j++) {
                float wv[4];
#pragma unroll
                for (int c = 0; c < 4; c++) wv[c] = s_owT[j * 128 + tx + c * 32];
#pragma unroll
                for (int tt = 0; tt < 4; tt++) {
                    float xv = s_xo[(ty * 4 + tt) * NOUT + j];
#pragma unroll
                    for (int c = 0; c < 4; c++) acc[tt][c] += xv * wv[c];
                }
            }
#pragma unroll
            for (int tt = 0; tt < 4; tt++)
#pragma unroll
                for (int c = 0; c < 4; c++)
                    out[(size_t)(tbase + ty * 4 + tt) * OUTF + obase + tx + c * 32] = acc[tt][c];
        }
        __syncthreads();
    }
    if (tid == 0) red_rel_gpu(&g_pfcnt, nrows);

    // ================= main phase =================
    if (wid == 16) {
        // ---- producer warp: TMA for A + direct pack of B into smem stage ----
        if (lane == 0) {
            while (ld_acq_gpu(&g_qcnt) != TOK) __nanosleep(64);
        }
        __syncwarp();
        FENCE_PROXY_ASYNC();   // generic g_xq writes (via release/acquire) -> async proxy

#pragma unroll 1
        for (int it = 0; it < nunits; it++) {
            const int g = g0 + it;
            const int fs = it & (STAGES - 1);
            const int nt = g >> 5, k = g & 31;
            if (it >= STAGES) {
                if (lane == 0) MBARRIER_WAIT_PARITY(sb + MBE_OFF + fs * 8, ((it >> 2) - 1) & 1);
                __syncwarp();
            }
            const uint32_t mb = sb + MBF_OFF + fs * 8;
            if (lane == 0) {
                MBARRIER_EXPECT_TX(mb, 2 * AHALF);
                BULK_G2S(sb + SA_OFF(fs),         g_xq + ((size_t)k << 14),        AHALF, mb);
                BULK_G2S(sb + SA_OFF(fs) + AHALF, g_xq + ((size_t)(32 + k) << 14), AHALF, mb);
            }
            // pack B block (64 rows x 128 int32) -> 8KB swizzled int8 in smem.
            // Row r: warp-wide coalesced 512B load; lane covers out bytes [4*lane,4*lane+4).
            const int* wsrc = w + (size_t)(nt * 64) * INF + k * 128;
            const uint32_t bstage = sb + SA_OFF(fs) + 2 * AHALF;
            const uint32_t lcol = ((uint32_t)lane & 3) * 4;
            const uint32_t lgrp = (uint32_t)lane >> 2;
#pragma unroll 1
            for (int rb = 0; rb < 64; rb += 8) {
                int4 v[8];
#pragma unroll
                for (int i = 0; i < 8; i++)
                    v[i] = ((const int4*)(wsrc + (size_t)(rb + i) * INF))[lane];
#pragma unroll
                for (int i = 0; i < 8; i++) {
                    const int r = rb + i;
                    uint32_t pk = __byte_perm(
                        __byte_perm((uint32_t)v[i].x, (uint32_t)v[i].y, 0x0040),
                        __byte_perm((uint32_t)v[i].z, (uint32_t)v[i].w, 0x0040), 0x5410);
                    uint32_t off = (uint32_t)r * 128 + ((lgrp ^ (uint32_t)(r & 7)) << 4) + lcol;
                    asm volatile("st.shared.b32 [%0], %1;" :: "r"(bstage + off), "r"(pk) : "memory");
                }
            }
            __syncwarp();
            if (lane == 0) MBARRIER_ARRIVE(mb);   // release: B STS visible at flip
        }
    } else {
        // ---- consumers: pure IMMA loop, 16 warps (4m x 4n over m256 x n64) ----
        const int wm = wid >> 2, wn = wid & 3;
        const float inv = 1.0f / 16129.0f;
        const int grp = lane >> 2, qid = lane & 3;
        bool pfok = false;

        int acc[4][2][4];
#pragma unroll
        for (int i = 0; i < 4; i++)
#pragma unroll
            for (int j = 0; j < 2; j++)
#pragma unroll
                for (int q = 0; q < 4; q++) acc[i][j][q] = 0;

#pragma unroll 1
        for (int c = 0; c < nunits; c++) {
            const int g = g0 + c;
            const int s = c & (STAGES - 1);
            MBARRIER_WAIT_PARITY(sb + MBF_OFF + s * 8, (c >> 2) & 1);

#pragma unroll
            for (int ksl = 0; ksl < 4; ksl++) {
                uint32_t a[4][4];
#pragma unroll
                for (int mf = 0; mf < 4; mf++) {
                    int absrow = wm * 64 + mf * 16 + (lane & 15);
                    int blk = absrow >> 7, inner = absrow & 127;
                    int kc = 2 * ksl + (lane >> 4);
                    uint32_t ad = sb + SA_OFF(s) + blk * AHALF +
                                  (uint32_t)(inner * 128 + ((kc ^ (inner & 7)) << 4));
                    asm volatile("ldmatrix.sync.aligned.m8n8.x4.shared.b16 {%0,%1,%2,%3}, [%4];"
                        : "=r"(a[mf][0]), "=r"(a[mf][1]), "=r"(a[mf][2]), "=r"(a[mf][3])
                        : "r"(ad));
                }
                uint32_t b[4];
                {
                    int n = wn * 16 + (lane & 7) + ((lane >> 4) << 3);
                    int kc = 2 * ksl + ((lane >> 3) & 1);
                    uint32_t bd = sb + SA_OFF(s) + 2 * AHALF +
                                  (uint32_t)(n * 128 + ((kc ^ (n & 7)) << 4));
                    asm volatile("ldmatrix.sync.aligned.m8n8.x4.shared.b16 {%0,%1,%2,%3}, [%4];"
                        : "=r"(b[0]), "=r"(b[1]), "=r"(b[2]), "=r"(b[3])
                        : "r"(bd));
                }
#pragma unroll
                for (int mf = 0; mf < 4; mf++)
#pragma unroll
                    for (int nf = 0; nf < 2; nf++) {
                        asm volatile(
                            "mma.sync.aligned.m16n8k32.row.col.s32.s8.s8.s32 "
                            "{%0,%1,%2,%3}, {%4,%5,%6,%7}, {%8,%9}, {%0,%1,%2,%3};"
                            : "+r"(acc[mf][nf][0]), "+r"(acc[mf][nf][1]),
                              "+r"(acc[mf][nf][2]), "+r"(acc[mf][nf][3])
                            : "r"(a[mf][0]), "r"(a[mf][1]), "r"(a[mf][2]), "r"(a[mf][3]),
                              "r"(b[nf * 2]), "r"(b[nf * 2 + 1]));
                    }
            }
            MBARRIER_ARRIVE(sb + MBE_OFF + s * 8);

            // ---- epilogue at nt boundary or range end ----
            if (c + 1 == nunits || ((g + 1) & 31) == 0) {
                if (!pfok) {
                    while (ld_acq_gpu(&g_pfcnt) != 256) __nanosleep(64);
                    pfok = true;
                }
                const int nbase = (g >> 5) * 64;
#pragma unroll
                for (int mf = 0; mf < 4; mf++) {
                    const int m0 = wm * 64 + mf * 16 + grp;
                    const float s0 = g_xs[m0] * inv;
                    const float s1 = g_xs[m0 + 8] * inv;
#pragma unroll
                    for (int nf = 0; nf < 2; nf++) {
                        const int o = nbase + wn * 16 + nf * 8 + qid * 2;
                        const float2 wsv = *(const float2*)(wscale + o);
                        float* p0 = out + (size_t)m0 * OUTF + o;
                        float* p1 = out + (size_t)(m0 + 8) * OUTF + o;
                        atomicAdd(p0,     (float)acc[mf][nf][0] * (s0 * wsv.x));
                        atomicAdd(p0 + 1, (float)acc[mf][nf][1] * (s0 * wsv.y));
                        atomicAdd(p1,     (float)acc[mf][nf][2] * (s1 * wsv.x));
                        atomicAdd(p1 + 1, (float)acc[mf][nf][3] * (s1 * wsv.y));
                    }
                }
#pragma unroll
                for (int i = 0; i < 4; i++)
#pragma unroll
                    for (int j = 0; j < 2; j++)
#pragma unroll
                        for (int q = 0; q < 4; q++) acc[i][j][q] = 0;
            }
        }
    }
}

// ---------------- launch ----------------
extern "C" void kernel_launch(void* const* d_in, const int* in_sizes, int n_in,
                              void* d_out, int out_size) {
    const float* x    = (const float*)d_in[0];
    const int*   w    = (const int*)d_in[1];
    const float* ws   = (const float*)d_in[2];
    const int*   oidx = (const int*)d_in[3];
    const float* ow   = (const float*)d_in[4];
    const float* bias = (const float*)d_in[5];
    float* out = (float*)d_out;

    cudaFuncSetAttribute(fused_kernel, cudaFuncAttributeMaxDynamicSharedMemorySize, SMEM_TOTAL);

    reset_kernel<<<1, 1>>>();
    fused_kernel<<<NCTA, 544, SMEM_TOTAL>>>(x, w, oidx, ow, bias, ws, out);
}